// round 1
// baseline (speedup 1.0000x reference)
#include <cuda_runtime.h>

// Problem constants
#define BC    2
#define NQC   2048
#define NKC   2048
#define DIMC  1024
#define HC    16
#define HDC   32
#define D2C   64
#define LAMBDA_INIT_F 0.6192834728526787f
#define ONE_MINUS_LAMBDA_F 0.3807165271473213f
#define SCALE_F 0.17677669529663687f
#define EPS_F 1e-5f

// Scratch (device globals — no runtime allocation allowed)
__device__ float g_Q[(size_t)BC * NQC * DIMC];
__device__ float g_K[(size_t)BC * NKC * DIMC];
__device__ float g_V[(size_t)BC * NKC * DIMC];
__device__ float g_A[(size_t)BC * NQC * DIMC];
__device__ float g_lam;

// ---------------------------------------------------------------------------
// lambda = exp(sum(lq1*lk1)) - exp(sum(lq2*lk2)) + LAMBDA_INIT
// ---------------------------------------------------------------------------
__global__ void lam_kernel(const float* __restrict__ lq1, const float* __restrict__ lk1,
                           const float* __restrict__ lq2, const float* __restrict__ lk2) {
    int i = threadIdx.x;  // 32 threads
    float p1 = lq1[i] * lk1[i];
    float p2 = lq2[i] * lk2[i];
    #pragma unroll
    for (int o = 16; o > 0; o >>= 1) {
        p1 += __shfl_xor_sync(0xffffffffu, p1, o);
        p2 += __shfl_xor_sync(0xffffffffu, p2, o);
    }
    if (i == 0) g_lam = expf(p1) - expf(p2) + LAMBDA_INIT_F;
}

// ---------------------------------------------------------------------------
// C[M,N] = A[M,K] @ B[N,K]^T (+ bias[n]), fp32, 128x128x8 tiles, 8x8/thread
// ---------------------------------------------------------------------------
__global__ __launch_bounds__(256) void gemm_nt(const float* __restrict__ A,
                                               const float* __restrict__ B,
                                               const float* __restrict__ bias,
                                               float* __restrict__ C,
                                               int M, int N, int K) {
    __shared__ float As[8][128];
    __shared__ float Bs[8][128];

    const int tid  = threadIdx.x;
    const int lrow = tid >> 1;
    const int lk4  = (tid & 1) * 4;
    const int tx   = tid & 15;
    const int ty   = tid >> 4;

    const float* Ap = A + (size_t)(blockIdx.y * 128 + lrow) * K + lk4;
    const float* Bp = B + (size_t)(blockIdx.x * 128 + lrow) * K + lk4;

    float acc[8][8];
    #pragma unroll
    for (int i = 0; i < 8; i++)
        #pragma unroll
        for (int j = 0; j < 8; j++) acc[i][j] = 0.0f;

    for (int kb = 0; kb < K; kb += 8) {
        float4 a4 = *(const float4*)(Ap + kb);
        float4 b4 = *(const float4*)(Bp + kb);
        __syncthreads();
        As[lk4 + 0][lrow] = a4.x; As[lk4 + 1][lrow] = a4.y;
        As[lk4 + 2][lrow] = a4.z; As[lk4 + 3][lrow] = a4.w;
        Bs[lk4 + 0][lrow] = b4.x; Bs[lk4 + 1][lrow] = b4.y;
        Bs[lk4 + 2][lrow] = b4.z; Bs[lk4 + 3][lrow] = b4.w;
        __syncthreads();
        #pragma unroll
        for (int k = 0; k < 8; k++) {
            float a[8], b[8];
            *(float4*)(a)     = *(const float4*)&As[k][ty * 8];
            *(float4*)(a + 4) = *(const float4*)&As[k][ty * 8 + 4];
            *(float4*)(b)     = *(const float4*)&Bs[k][tx * 8];
            *(float4*)(b + 4) = *(const float4*)&Bs[k][tx * 8 + 4];
            #pragma unroll
            for (int i = 0; i < 8; i++)
                #pragma unroll
                for (int j = 0; j < 8; j++) acc[i][j] += a[i] * b[j];
        }
    }

    const int cn = blockIdx.x * 128 + tx * 8;
    float bvals[8];
    #pragma unroll
    for (int j = 0; j < 8; j++) bvals[j] = bias ? bias[cn + j] : 0.0f;

    #pragma unroll
    for (int i = 0; i < 8; i++) {
        float* crow = C + (size_t)(blockIdx.y * 128 + ty * 8 + i) * N + cn;
        float4 r0, r1;
        r0.x = acc[i][0] + bvals[0]; r0.y = acc[i][1] + bvals[1];
        r0.z = acc[i][2] + bvals[2]; r0.w = acc[i][3] + bvals[3];
        r1.x = acc[i][4] + bvals[4]; r1.y = acc[i][5] + bvals[5];
        r1.z = acc[i][6] + bvals[6]; r1.w = acc[i][7] + bvals[7];
        *(float4*)(crow)     = r0;
        *(float4*)(crow + 4) = r1;
    }
}

// ---------------------------------------------------------------------------
// Fused dual-stream flash attention + lambda combine + RMSNorm + subln_w
// Grid: (B*H, NQ/16), 128 threads. Each block: 16 q rows, one (b,h).
// Thread (r = tid>>3, c = tid&7): q-row r, keys {j*8+c}, out dims c*8..c*8+7.
// ---------------------------------------------------------------------------
__global__ __launch_bounds__(128) void attn_kernel(const float* __restrict__ subw) {
    __shared__ float sQ1[16][33];
    __shared__ float sQ2[16][33];
    __shared__ float sK1[64][33];
    __shared__ float sK2[64][33];
    __shared__ float sV[64][64];
    __shared__ float sP1[16][65];
    __shared__ float sP2[16][65];

    const int b  = blockIdx.x >> 4;
    const int h  = blockIdx.x & 15;
    const int q0 = blockIdx.y << 4;
    const int tid = threadIdx.x;
    const int r = tid >> 3;
    const int c = tid & 7;

    const float lam = g_lam;

    const float* Qb = g_Q + ((size_t)b * NQC + q0) * DIMC + h * HDC;
    const float* Kb = g_K + ((size_t)b * NKC) * DIMC + h * HDC;
    const float* Vb = g_V + ((size_t)b * NKC) * DIMC + h * D2C;

    // Load Q tiles (pre-scaled by SCALE). 256 float4 slots, 2 per thread.
    #pragma unroll
    for (int s = tid; s < 256; s += 128) {
        int st  = s >> 7;
        int row = (s >> 3) & 15;
        int d4  = (s & 7) * 4;
        float4 v4 = *(const float4*)(Qb + (size_t)row * DIMC + st * (HC * HDC) + d4);
        float* dst = st ? &sQ2[row][0] : &sQ1[row][0];
        dst[d4 + 0] = v4.x * SCALE_F; dst[d4 + 1] = v4.y * SCALE_F;
        dst[d4 + 2] = v4.z * SCALE_F; dst[d4 + 3] = v4.w * SCALE_F;
    }

    float m1 = -1e30f, l1 = 0.0f;
    float m2 = -1e30f, l2 = 0.0f;
    float o1[8], o2[8];
    #pragma unroll
    for (int j = 0; j < 8; j++) { o1[j] = 0.0f; o2[j] = 0.0f; }

    for (int kt = 0; kt < NKC / 64; kt++) {
        const int k0 = kt * 64;
        __syncthreads();  // previous iteration's smem reads done

        // Load K1,K2 tiles: 1024 float4 slots
        #pragma unroll
        for (int s = tid; s < 1024; s += 128) {
            int st = s >> 9;
            int kk = (s >> 3) & 63;
            int d4 = (s & 7) * 4;
            float4 v4 = *(const float4*)(Kb + (size_t)(k0 + kk) * DIMC + st * (HC * HDC) + d4);
            float* dst = st ? &sK2[kk][0] : &sK1[kk][0];
            dst[d4 + 0] = v4.x; dst[d4 + 1] = v4.y;
            dst[d4 + 2] = v4.z; dst[d4 + 3] = v4.w;
        }
        // Load V tile: 1024 float4 slots
        #pragma unroll
        for (int s = tid; s < 1024; s += 128) {
            int kk = s >> 4;
            int d4 = (s & 15) * 4;
            *(float4*)&sV[kk][d4] = *(const float4*)(Vb + (size_t)(k0 + kk) * DIMC + d4);
        }
        __syncthreads();

        // Scores for this thread's keys: kk = j*8 + c  (conflict-free banks)
        float s1[8], s2[8];
        #pragma unroll
        for (int j = 0; j < 8; j++) { s1[j] = 0.0f; s2[j] = 0.0f; }
        #pragma unroll
        for (int d = 0; d < 32; d++) {
            float q1v = sQ1[r][d];
            float q2v = sQ2[r][d];
            #pragma unroll
            for (int j = 0; j < 8; j++) {
                s1[j] += q1v * sK1[j * 8 + c][d];
                s2[j] += q2v * sK2[j * 8 + c][d];
            }
        }

        // Online softmax, stream 1
        float mt1 = s1[0], mt2 = s2[0];
        #pragma unroll
        for (int j = 1; j < 8; j++) { mt1 = fmaxf(mt1, s1[j]); mt2 = fmaxf(mt2, s2[j]); }
        #pragma unroll
        for (int o = 1; o < 8; o <<= 1) {
            mt1 = fmaxf(mt1, __shfl_xor_sync(0xffffffffu, mt1, o));
            mt2 = fmaxf(mt2, __shfl_xor_sync(0xffffffffu, mt2, o));
        }
        float m1n = fmaxf(m1, mt1);
        float m2n = fmaxf(m2, mt2);
        float a1 = __expf(m1 - m1n);
        float a2 = __expf(m2 - m2n);
        float ls1 = 0.0f, ls2 = 0.0f;
        #pragma unroll
        for (int j = 0; j < 8; j++) {
            float p1 = __expf(s1[j] - m1n);
            float p2 = __expf(s2[j] - m2n);
            ls1 += p1; ls2 += p2;
            sP1[r][j * 8 + c] = p1;
            sP2[r][j * 8 + c] = p2;
        }
        #pragma unroll
        for (int o = 1; o < 8; o <<= 1) {
            ls1 += __shfl_xor_sync(0xffffffffu, ls1, o);
            ls2 += __shfl_xor_sync(0xffffffffu, ls2, o);
        }
        l1 = l1 * a1 + ls1;  m1 = m1n;
        l2 = l2 * a2 + ls2;  m2 = m2n;
        #pragma unroll
        for (int j = 0; j < 8; j++) { o1[j] *= a1; o2[j] *= a2; }

        __syncthreads();  // sP visible to all

        // PV accumulate: out dims c*8 .. c*8+7
        #pragma unroll
        for (int kk = 0; kk < 64; kk++) {
            float p1v = sP1[r][kk];
            float p2v = sP2[r][kk];
            float4 va = *(const float4*)&sV[kk][c * 8];
            float4 vb = *(const float4*)&sV[kk][c * 8 + 4];
            o1[0] += p1v * va.x; o1[1] += p1v * va.y; o1[2] += p1v * va.z; o1[3] += p1v * va.w;
            o1[4] += p1v * vb.x; o1[5] += p1v * vb.y; o1[6] += p1v * vb.z; o1[7] += p1v * vb.w;
            o2[0] += p2v * va.x; o2[1] += p2v * va.y; o2[2] += p2v * va.z; o2[3] += p2v * va.w;
            o2[4] += p2v * vb.x; o2[5] += p2v * vb.y; o2[6] += p2v * vb.z; o2[7] += p2v * vb.w;
        }
    }

    // Epilogue: combine, RMSNorm over 64 dims, scale, write
    float inv1 = 1.0f / l1;
    float inv2 = lam / l2;
    float outv[8];
    float ss = 0.0f;
    #pragma unroll
    for (int j = 0; j < 8; j++) {
        outv[j] = o1[j] * inv1 - o2[j] * inv2;
        ss += outv[j] * outv[j];
    }
    #pragma unroll
    for (int o = 1; o < 8; o <<= 1) ss += __shfl_xor_sync(0xffffffffu, ss, o);
    float rinv = rsqrtf(ss * (1.0f / 64.0f) + EPS_F);

    float* dst = g_A + ((size_t)b * NQC + q0 + r) * DIMC + h * D2C + c * 8;
    #pragma unroll
    for (int j = 0; j < 8; j++)
        dst[j] = outv[j] * rinv * subw[c * 8 + j] * ONE_MINUS_LAMBDA_F;
}

// ---------------------------------------------------------------------------
extern "C" void kernel_launch(void* const* d_in, const int* in_sizes, int n_in,
                              void* d_out, int out_size) {
    const float* query = (const float*)d_in[0];
    const float* key_  = (const float*)d_in[1];
    const float* value = (const float*)d_in[2];
    const float* Wq    = (const float*)d_in[3];
    const float* Wk    = (const float*)d_in[4];
    const float* Wv    = (const float*)d_in[5];
    const float* Wp    = (const float*)d_in[6];
    const float* bp    = (const float*)d_in[7];
    const float* lq1   = (const float*)d_in[8];
    const float* lk1   = (const float*)d_in[9];
    const float* lq2   = (const float*)d_in[10];
    const float* lk2   = (const float*)d_in[11];
    const float* subw  = (const float*)d_in[12];
    float* out = (float*)d_out;

    float *Qp, *Kp, *Vp, *Ap;
    cudaGetSymbolAddress((void**)&Qp, g_Q);
    cudaGetSymbolAddress((void**)&Kp, g_K);
    cudaGetSymbolAddress((void**)&Vp, g_V);
    cudaGetSymbolAddress((void**)&Ap, g_A);

    const int M = BC * NQC;   // 4096
    const int N = DIMC;       // 1024
    const int K = DIMC;       // 1024
    dim3 ggrid(N / 128, M / 128);  // (8, 32)

    lam_kernel<<<1, 32>>>(lq1, lk1, lq2, lk2);
    gemm_nt<<<ggrid, 256>>>(query, Wq, nullptr, Qp, M, N, K);
    gemm_nt<<<ggrid, 256>>>(key_,  Wk, nullptr, Kp, M, N, K);
    gemm_nt<<<ggrid, 256>>>(value, Wv, nullptr, Vp, M, N, K);

    dim3 agrid(BC * HC, NQC / 16);  // (32, 128)
    attn_kernel<<<agrid, 128>>>(subw);

    gemm_nt<<<ggrid, 256>>>(Ap, Wp, bp, out, M, N, K);
}

// round 2
// speedup vs baseline: 5.4868x; 5.4868x over previous
#include <cuda_runtime.h>
#include <cstdint>

// Problem constants
#define BC    2
#define NQC   2048
#define NKC   2048
#define DIMC  1024
#define HC    16
#define HDC   32
#define D2C   64
#define LAMBDA_INIT_F 0.6192834728526787f
#define ONE_MINUS_LAMBDA_F 0.3807165271473213f
#define SCALE_F 0.17677669529663687f
#define EPS_F 1e-5f

// Scratch (device globals — no runtime allocation allowed)
__device__ float g_Q[(size_t)BC * NQC * DIMC];
__device__ float g_K[(size_t)BC * NKC * DIMC];
__device__ float g_V[(size_t)BC * NKC * DIMC];
__device__ float g_A[(size_t)BC * NQC * DIMC];
__device__ float g_lam;

// ---------------------------------------------------------------------------
// helpers
// ---------------------------------------------------------------------------
__device__ __forceinline__ uint32_t f2tf(float x) {
    uint32_t u;
    asm("cvt.rna.tf32.f32 %0, %1;" : "=r"(u) : "f"(x));
    return u;
}

__device__ __forceinline__ void mma8(float (&d)[4], const uint32_t (&a)[4],
                                     const uint32_t (&b)[2]) {
    asm volatile(
        "mma.sync.aligned.m16n8k8.row.col.f32.tf32.tf32.f32 "
        "{%0,%1,%2,%3},{%4,%5,%6,%7},{%8,%9},{%0,%1,%2,%3};"
        : "+f"(d[0]), "+f"(d[1]), "+f"(d[2]), "+f"(d[3])
        : "r"(a[0]), "r"(a[1]), "r"(a[2]), "r"(a[3]), "r"(b[0]), "r"(b[1]));
}

// ---------------------------------------------------------------------------
// lambda = exp(sum(lq1*lk1)) - exp(sum(lq2*lk2)) + LAMBDA_INIT
// ---------------------------------------------------------------------------
__global__ void lam_kernel(const float* __restrict__ lq1, const float* __restrict__ lk1,
                           const float* __restrict__ lq2, const float* __restrict__ lk2) {
    int i = threadIdx.x;  // 32 threads
    float p1 = lq1[i] * lk1[i];
    float p2 = lq2[i] * lk2[i];
    #pragma unroll
    for (int o = 16; o > 0; o >>= 1) {
        p1 += __shfl_xor_sync(0xffffffffu, p1, o);
        p2 += __shfl_xor_sync(0xffffffffu, p2, o);
    }
    if (i == 0) g_lam = expf(p1) - expf(p2) + LAMBDA_INIT_F;
}

// ---------------------------------------------------------------------------
// C[M,N] = A[M,K] @ B[N,K]^T (+ bias), tf32 tensor-core GEMM.
// 128x128 block tile, 8 warps (2 along M x 4 along N), warp tile 64x32.
// K-block = 32 (4 mma k-steps). smem pitch 36 -> conflict-free frag loads.
// ---------------------------------------------------------------------------
__global__ __launch_bounds__(256) void gemm_tf32(const float* __restrict__ A,
                                                 const float* __restrict__ B,
                                                 const float* __restrict__ bias,
                                                 float* __restrict__ C,
                                                 int M, int N, int K) {
    __shared__ float As[128][36];
    __shared__ float Bs[128][36];

    const int tid  = threadIdx.x;
    const int w    = tid >> 5;
    const int lane = tid & 31;
    const int gid  = lane >> 2;
    const int t    = lane & 3;
    const int wm   = w & 1;    // 0..1
    const int wn   = w >> 1;   // 0..3

    const int brow = blockIdx.y * 128;
    const int bcol = blockIdx.x * 128;

    const float* Ag = A + (size_t)brow * K;
    const float* Bg = B + (size_t)bcol * K;

    float acc[4][4][4];
    #pragma unroll
    for (int mt = 0; mt < 4; mt++)
        #pragma unroll
        for (int nt = 0; nt < 4; nt++)
            #pragma unroll
            for (int r = 0; r < 4; r++) acc[mt][nt][r] = 0.0f;

    for (int kb = 0; kb < K; kb += 32) {
        __syncthreads();
        #pragma unroll
        for (int i = 0; i < 4; i++) {
            int slot = tid + 256 * i;
            int row  = slot >> 3;
            int k4   = (slot & 7) * 4;
            float4 av = *(const float4*)(Ag + (size_t)row * K + kb + k4);
            float4 bv = *(const float4*)(Bg + (size_t)row * K + kb + k4);
            As[row][k4 + 0] = __uint_as_float(f2tf(av.x));
            As[row][k4 + 1] = __uint_as_float(f2tf(av.y));
            As[row][k4 + 2] = __uint_as_float(f2tf(av.z));
            As[row][k4 + 3] = __uint_as_float(f2tf(av.w));
            Bs[row][k4 + 0] = __uint_as_float(f2tf(bv.x));
            Bs[row][k4 + 1] = __uint_as_float(f2tf(bv.y));
            Bs[row][k4 + 2] = __uint_as_float(f2tf(bv.z));
            Bs[row][k4 + 3] = __uint_as_float(f2tf(bv.w));
        }
        __syncthreads();

        #pragma unroll
        for (int k = 0; k < 4; k++) {
            uint32_t af[4][4];
            uint32_t bf[4][2];
            #pragma unroll
            for (int mt = 0; mt < 4; mt++) {
                int r = wm * 64 + mt * 16;
                af[mt][0] = __float_as_uint(As[r + gid][k * 8 + t]);
                af[mt][1] = __float_as_uint(As[r + gid + 8][k * 8 + t]);
                af[mt][2] = __float_as_uint(As[r + gid][k * 8 + t + 4]);
                af[mt][3] = __float_as_uint(As[r + gid + 8][k * 8 + t + 4]);
            }
            #pragma unroll
            for (int nt = 0; nt < 4; nt++) {
                int r = wn * 32 + nt * 8;
                bf[nt][0] = __float_as_uint(Bs[r + gid][k * 8 + t]);
                bf[nt][1] = __float_as_uint(Bs[r + gid][k * 8 + t + 4]);
            }
            #pragma unroll
            for (int mt = 0; mt < 4; mt++)
                #pragma unroll
                for (int nt = 0; nt < 4; nt++)
                    mma8(acc[mt][nt], af[mt], bf[nt]);
        }
    }

    // epilogue
    #pragma unroll
    for (int mt = 0; mt < 4; mt++) {
        int row = brow + wm * 64 + mt * 16 + gid;
        #pragma unroll
        for (int nt = 0; nt < 4; nt++) {
            int col = bcol + wn * 32 + nt * 8 + 2 * t;
            float b0 = 0.0f, b1 = 0.0f;
            if (bias) { b0 = bias[col]; b1 = bias[col + 1]; }
            float2 v0 = make_float2(acc[mt][nt][0] + b0, acc[mt][nt][1] + b1);
            float2 v1 = make_float2(acc[mt][nt][2] + b0, acc[mt][nt][3] + b1);
            *(float2*)(C + (size_t)row * N + col)       = v0;
            *(float2*)(C + (size_t)(row + 8) * N + col) = v1;
        }
    }
}

// ---------------------------------------------------------------------------
// Fused dual-stream flash attention (tf32 mma) + lambda + RMSNorm + subln
// Grid: (B*H=32, NQ/64=32), 256 threads = 8 warps.
// Warp w: stream s = w>>2, q-slab qs = (w&3)*16 (16 q-rows per warp).
// K-tile = 32 keys per iteration.
// ---------------------------------------------------------------------------
__global__ __launch_bounds__(256) void attn_kernel(const float* __restrict__ subw) {
    __shared__ float sK[2][32][36];   // [stream][key][dim]
    __shared__ float sV[32][72];      // [key][vdim]
    __shared__ float sP[2][64][36];   // [stream][qrow][key]  (also reused as sX)

    const int b   = blockIdx.x >> 4;
    const int h   = blockIdx.x & 15;
    const int q0  = blockIdx.y << 6;
    const int tid = threadIdx.x;
    const int w    = tid >> 5;
    const int lane = tid & 31;
    const int s    = w >> 2;          // stream 0/1
    const int qs   = (w & 3) << 4;    // q-slab base within 64
    const int gid  = lane >> 2;
    const int t    = lane & 3;

    const float* Qb = g_Q + ((size_t)b * NQC + q0) * DIMC + h * HDC;
    const float* Kb = g_K + (size_t)b * NKC * DIMC + h * HDC;
    const float* Vb = g_V + (size_t)b * NKC * DIMC + h * D2C;

    // Q fragments (persist in registers, pre-scaled, tf32-rounded)
    uint32_t aQ[4][4];
    {
        const float* qr0 = Qb + (size_t)(qs + gid) * DIMC + s * (HC * HDC);
        const float* qr1 = qr0 + (size_t)8 * DIMC;
        #pragma unroll
        for (int k = 0; k < 4; k++) {
            aQ[k][0] = f2tf(qr0[k * 8 + t] * SCALE_F);
            aQ[k][1] = f2tf(qr1[k * 8 + t] * SCALE_F);
            aQ[k][2] = f2tf(qr0[k * 8 + t + 4] * SCALE_F);
            aQ[k][3] = f2tf(qr1[k * 8 + t + 4] * SCALE_F);
        }
    }

    float m0 = -1e30f, m1 = -1e30f, l0 = 0.0f, l1 = 0.0f;
    float O[8][4];
    #pragma unroll
    for (int n = 0; n < 8; n++)
        #pragma unroll
        for (int r = 0; r < 4; r++) O[n][r] = 0.0f;

    const float* sKs = &sK[s][0][0];
    float*       sPs = &sP[s][0][0];

    for (int kt = 0; kt < NKC / 32; kt++) {
        const int k0 = kt * 32;
        __syncthreads();  // previous iteration's K/V reads done

        // Load K (both streams): 2048 floats = 512 float4, 2 per thread
        #pragma unroll
        for (int i = 0; i < 2; i++) {
            int slot = tid + 256 * i;
            int st   = slot >> 8;
            int key  = (slot >> 3) & 31;
            int d4   = (slot & 7) * 4;
            float4 v4 = *(const float4*)(Kb + (size_t)(k0 + key) * DIMC + st * (HC * HDC) + d4);
            float* dst = &sK[st][key][d4];
            dst[0] = __uint_as_float(f2tf(v4.x));
            dst[1] = __uint_as_float(f2tf(v4.y));
            dst[2] = __uint_as_float(f2tf(v4.z));
            dst[3] = __uint_as_float(f2tf(v4.w));
        }
        // Load V: 2048 floats
        #pragma unroll
        for (int i = 0; i < 2; i++) {
            int slot = tid + 256 * i;
            int key  = slot >> 4;
            int d4   = (slot & 15) * 4;
            float4 v4 = *(const float4*)(Vb + (size_t)(k0 + key) * DIMC + d4);
            float* dst = &sV[key][d4];
            dst[0] = __uint_as_float(f2tf(v4.x));
            dst[1] = __uint_as_float(f2tf(v4.y));
            dst[2] = __uint_as_float(f2tf(v4.z));
            dst[3] = __uint_as_float(f2tf(v4.w));
        }
        __syncthreads();

        // S = Q(16x32) x K^T (keys as N)  -> 4 n-tiles x 4 k-steps
        float S[4][4];
        #pragma unroll
        for (int n = 0; n < 4; n++)
            #pragma unroll
            for (int r = 0; r < 4; r++) S[n][r] = 0.0f;

        #pragma unroll
        for (int k = 0; k < 4; k++) {
            #pragma unroll
            for (int n = 0; n < 4; n++) {
                uint32_t bf[2];
                bf[0] = __float_as_uint(sKs[(n * 8 + gid) * 36 + k * 8 + t]);
                bf[1] = __float_as_uint(sKs[(n * 8 + gid) * 36 + k * 8 + t + 4]);
                mma8(S[n], aQ[k], bf);
            }
        }

        // online softmax (row gid -> m0/l0, row gid+8 -> m1/l1)
        float mt0 = -1e30f, mt1 = -1e30f;
        #pragma unroll
        for (int n = 0; n < 4; n++) {
            mt0 = fmaxf(mt0, fmaxf(S[n][0], S[n][1]));
            mt1 = fmaxf(mt1, fmaxf(S[n][2], S[n][3]));
        }
        mt0 = fmaxf(mt0, __shfl_xor_sync(0xffffffffu, mt0, 1));
        mt0 = fmaxf(mt0, __shfl_xor_sync(0xffffffffu, mt0, 2));
        mt1 = fmaxf(mt1, __shfl_xor_sync(0xffffffffu, mt1, 1));
        mt1 = fmaxf(mt1, __shfl_xor_sync(0xffffffffu, mt1, 2));

        float mn0 = fmaxf(m0, mt0);
        float mn1 = fmaxf(m1, mt1);
        float a0 = __expf(m0 - mn0);
        float a1 = __expf(m1 - mn1);
        m0 = mn0; m1 = mn1;

        float ls0 = 0.0f, ls1 = 0.0f;
        #pragma unroll
        for (int n = 0; n < 4; n++) {
            float p0 = __expf(S[n][0] - mn0);
            float p1 = __expf(S[n][1] - mn0);
            float p2 = __expf(S[n][2] - mn1);
            float p3 = __expf(S[n][3] - mn1);
            ls0 += p0 + p1;
            ls1 += p2 + p3;
            sPs[(qs + gid) * 36 + n * 8 + 2 * t]         = __uint_as_float(f2tf(p0));
            sPs[(qs + gid) * 36 + n * 8 + 2 * t + 1]     = __uint_as_float(f2tf(p1));
            sPs[(qs + gid + 8) * 36 + n * 8 + 2 * t]     = __uint_as_float(f2tf(p2));
            sPs[(qs + gid + 8) * 36 + n * 8 + 2 * t + 1] = __uint_as_float(f2tf(p3));
        }
        ls0 += __shfl_xor_sync(0xffffffffu, ls0, 1);
        ls0 += __shfl_xor_sync(0xffffffffu, ls0, 2);
        ls1 += __shfl_xor_sync(0xffffffffu, ls1, 1);
        ls1 += __shfl_xor_sync(0xffffffffu, ls1, 2);
        l0 = l0 * a0 + ls0;
        l1 = l1 * a1 + ls1;

        #pragma unroll
        for (int n = 0; n < 8; n++) {
            O[n][0] *= a0; O[n][1] *= a0;
            O[n][2] *= a1; O[n][3] *= a1;
        }
        __syncwarp();  // sP stores visible across warp lanes

        // O += P(16x32) x V(32x64)  -> 8 n-tiles x 4 k-steps
        #pragma unroll
        for (int k = 0; k < 4; k++) {
            uint32_t ap[4];
            ap[0] = __float_as_uint(sPs[(qs + gid) * 36 + k * 8 + t]);
            ap[1] = __float_as_uint(sPs[(qs + gid + 8) * 36 + k * 8 + t]);
            ap[2] = __float_as_uint(sPs[(qs + gid) * 36 + k * 8 + t + 4]);
            ap[3] = __float_as_uint(sPs[(qs + gid + 8) * 36 + k * 8 + t + 4]);
            #pragma unroll
            for (int n = 0; n < 8; n++) {
                uint32_t bf[2];
                bf[0] = __float_as_uint(sV[k * 8 + t][n * 8 + gid]);
                bf[1] = __float_as_uint(sV[k * 8 + t + 4][n * 8 + gid]);
                mma8(O[n], ap, bf);
            }
        }
        __syncwarp();  // sP reads done before next iteration's stores
    }

    // ---------------- epilogue ----------------
    __syncthreads();  // all PV reads of sP done before overlaying sX

    float* sX = &sP[0][0][0];  // 64 x 68 overlay (4352 <= 4608 floats)
    const float invl0 = 1.0f / l0;
    const float invl1 = 1.0f / l1;

    if (s == 1) {
        #pragma unroll
        for (int n = 0; n < 8; n++) {
            sX[(qs + gid) * 68 + n * 8 + 2 * t]         = O[n][0] * invl0;
            sX[(qs + gid) * 68 + n * 8 + 2 * t + 1]     = O[n][1] * invl0;
            sX[(qs + gid + 8) * 68 + n * 8 + 2 * t]     = O[n][2] * invl1;
            sX[(qs + gid + 8) * 68 + n * 8 + 2 * t + 1] = O[n][3] * invl1;
        }
    }
    __syncthreads();

    if (s == 0) {
        const float lam = g_lam;
        float out[8][4];
        float ss0 = 0.0f, ss1 = 0.0f;
        #pragma unroll
        for (int n = 0; n < 8; n++) {
            out[n][0] = O[n][0] * invl0 - lam * sX[(qs + gid) * 68 + n * 8 + 2 * t];
            out[n][1] = O[n][1] * invl0 - lam * sX[(qs + gid) * 68 + n * 8 + 2 * t + 1];
            out[n][2] = O[n][2] * invl1 - lam * sX[(qs + gid + 8) * 68 + n * 8 + 2 * t];
            out[n][3] = O[n][3] * invl1 - lam * sX[(qs + gid + 8) * 68 + n * 8 + 2 * t + 1];
            ss0 += out[n][0] * out[n][0] + out[n][1] * out[n][1];
            ss1 += out[n][2] * out[n][2] + out[n][3] * out[n][3];
        }
        ss0 += __shfl_xor_sync(0xffffffffu, ss0, 1);
        ss0 += __shfl_xor_sync(0xffffffffu, ss0, 2);
        ss1 += __shfl_xor_sync(0xffffffffu, ss1, 1);
        ss1 += __shfl_xor_sync(0xffffffffu, ss1, 2);
        float r0 = rsqrtf(ss0 * (1.0f / 64.0f) + EPS_F);
        float r1 = rsqrtf(ss1 * (1.0f / 64.0f) + EPS_F);

        float* d0 = g_A + ((size_t)b * NQC + q0 + qs + gid) * DIMC + h * D2C;
        float* d1 = d0 + (size_t)8 * DIMC;
        #pragma unroll
        for (int n = 0; n < 8; n++) {
            int c0 = n * 8 + 2 * t;
            float w0 = subw[c0] * ONE_MINUS_LAMBDA_F;
            float w1 = subw[c0 + 1] * ONE_MINUS_LAMBDA_F;
            d0[c0]     = out[n][0] * r0 * w0;
            d0[c0 + 1] = out[n][1] * r0 * w1;
            d1[c0]     = out[n][2] * r1 * w0;
            d1[c0 + 1] = out[n][3] * r1 * w1;
        }
    }
}

// ---------------------------------------------------------------------------
extern "C" void kernel_launch(void* const* d_in, const int* in_sizes, int n_in,
                              void* d_out, int out_size) {
    const float* query = (const float*)d_in[0];
    const float* key_  = (const float*)d_in[1];
    const float* value = (const float*)d_in[2];
    const float* Wq    = (const float*)d_in[3];
    const float* Wk    = (const float*)d_in[4];
    const float* Wv    = (const float*)d_in[5];
    const float* Wp    = (const float*)d_in[6];
    const float* bp    = (const float*)d_in[7];
    const float* lq1   = (const float*)d_in[8];
    const float* lk1   = (const float*)d_in[9];
    const float* lq2   = (const float*)d_in[10];
    const float* lk2   = (const float*)d_in[11];
    const float* subw  = (const float*)d_in[12];
    float* out = (float*)d_out;

    float *Qp, *Kp, *Vp, *Ap;
    cudaGetSymbolAddress((void**)&Qp, g_Q);
    cudaGetSymbolAddress((void**)&Kp, g_K);
    cudaGetSymbolAddress((void**)&Vp, g_V);
    cudaGetSymbolAddress((void**)&Ap, g_A);

    const int M = BC * NQC;   // 4096
    const int N = DIMC;       // 1024
    const int K = DIMC;       // 1024
    dim3 ggrid(N / 128, M / 128);  // (8, 32)

    lam_kernel<<<1, 32>>>(lq1, lk1, lq2, lk2);
    gemm_tf32<<<ggrid, 256>>>(query, Wq, nullptr, Qp, M, N, K);
    gemm_tf32<<<ggrid, 256>>>(key_,  Wk, nullptr, Kp, M, N, K);
    gemm_tf32<<<ggrid, 256>>>(value, Wv, nullptr, Vp, M, N, K);

    dim3 agrid(BC * HC, NQC / 64);  // (32, 32)
    attn_kernel<<<agrid, 256>>>(subw);

    gemm_tf32<<<ggrid, 256>>>(Ap, Wp, bp, out, M, N, K);
}